// round 2
// baseline (speedup 1.0000x reference)
#include <cuda_runtime.h>
#include <cstdint>

// ---------------------------------------------------------------------------
// RnnModelInterp: 2-layer tanh RNN, T=200 (199 output steps), B=256, H=512,
// NC=3, NM=64. Persistent single-kernel design:
//   - 128 CTAs (8 row-slices x 16 col-slices), 256 threads each, all co-resident
//   - each CTA caches its 32-column slice of W_ih0/W_hh0/W_ih1/W_hh1 (+ heads)
//     in SMEM once; recurrent state double-buffered in __device__ globals
//   - software grid barrier (monotonic counter) between the 3 phases per step
//   - inner GEMM loop uses packed fma.rn.f32x2 (2 MACs/instr) to reach the
//     128 fp32-MAC/cyc/SM fma-pipe floor
// ---------------------------------------------------------------------------

#define GRIDN    128
#define NTHREADS 256

#define T_STEPS 199
#define BATCH   256
#define H       512
#define NC      3
#define NM      64
#define NX      67            // NC + NM
#define KA      579           // NX + H
#define KA_PAD  608           // 19 * 32 (zero-padded)
#define KB      1024          // H + H
#define NCH_A   19
#define NCH_B   32
#define COLS    32            // output columns per CTA

// shared memory layout (float offsets)
#define OFF_W0  0
#define OFF_W1  (OFF_W0 + KA_PAD * COLS)      // 19456
#define OFF_HS  (OFF_W1 + KB * COLS)          // 52224
#define OFF_B0  (OFF_HS + 32 * 33)            // 53280
#define OFF_B1  (OFF_B0 + 32)                 // 53312
#define OFF_WM  (OFF_B1 + 32)                 // 53344 (4 x 516, transposed)
#define OFF_WC  (OFF_WM + 4 * 516)            // 55408 (3 x 516, transposed)
#define OFF_LG  (OFF_WC + 3 * 516)            // 56956 (32 rows x 3 logits)
#define SMEM_FLOATS (OFF_LG + 96)             // 57052
#define SMEM_BYTES  (SMEM_FLOATS * 4)         // 228208 < 232448 opt-in max

typedef unsigned long long ull;

// persistent state (device globals: no allocation in kernel_launch)
__device__ float g_h0[2][BATCH * H];
__device__ float g_h1[2][BATCH * H];
__device__ float g_X[BATCH * NX];             // imputed current input [cat|val]
__device__ ull   g_barcnt;                    // monotonic barrier counter

// ---------------------------------------------------------------------------
__device__ __forceinline__ ull fma2(ull a, ull b, ull c) {
    ull d;
    asm("fma.rn.f32x2 %0, %1, %2, %3;" : "=l"(d) : "l"(a), "l"(b), "l"(c));
    return d;
}

__device__ __forceinline__ void gridbar() {
    __syncthreads();
    if (threadIdx.x == 0) {
        __threadfence();
        ull old = atomicAdd(&g_barcnt, 1ULL);
        ull target = old - (old & (ull)(GRIDN - 1)) + (ull)GRIDN;
        while (*((volatile ull*)&g_barcnt) < target) { /* L2 spin */ }
        __threadfence();
    }
    __syncthreads();
}

// One fused GEMM phase: dst[r, colbase..colbase+31] =
//   tanh( sum_{k<ksplit} src0[r,k]*Ws[k,c] + sum_{ksplit<=k<ktot} src1[r,k-ksplit]*Ws[k,c] + bs[c] )
// for the 32 rows [rbase, rbase+32). Ws is the SMEM-resident weight slice.
__device__ __forceinline__ void mm_phase(
    const float* __restrict__ src0, int scols0, int ksplit,
    const float* __restrict__ src1, int ktot, int nchunks,
    const float* __restrict__ Ws, const float* __restrict__ bs,
    float* __restrict__ hs, float* __restrict__ dst,
    int rbase, int colbase)
{
    const int tid  = threadIdx.x;
    const int lane = tid & 31;
    const int w    = tid >> 5;   // warp 0..7 -> cols w*4 .. w*4+3

    // prefetch chunk 0 activations into registers
    float pv[4];
#pragma unroll
    for (int i = 0; i < 4; i++) {
        int idx = tid + i * NTHREADS;
        int row = idx >> 5, kk = idx & 31;
        int kg  = kk;
        float v = 0.f;
        if (kg < ksplit)    v = src0[(rbase + row) * scols0 + kg];
        else if (kg < ktot) v = src1[(rbase + row) * H + (kg - ksplit)];
        pv[i] = v;
    }

    ull acc0 = 0ULL, acc1 = 0ULL;
    for (int ch = 0; ch < nchunks; ch++) {
        __syncthreads();
#pragma unroll
        for (int i = 0; i < 4; i++) {
            int idx = tid + i * NTHREADS;
            hs[(idx >> 5) * 33 + (idx & 31)] = pv[i];
        }
        __syncthreads();
        if (ch + 1 < nchunks) {           // prefetch next chunk (overlaps compute)
            int k0n = (ch + 1) * 32;
#pragma unroll
            for (int i = 0; i < 4; i++) {
                int idx = tid + i * NTHREADS;
                int row = idx >> 5, kk = idx & 31;
                int kg  = k0n + kk;
                float v = 0.f;
                if (kg < ksplit)    v = src0[(rbase + row) * scols0 + kg];
                else if (kg < ktot) v = src1[(rbase + row) * H + (kg - ksplit)];
                pv[i] = v;
            }
        }
        const float* wrow = Ws + ch * 32 * COLS + (w << 2);
#pragma unroll 8
        for (int kk = 0; kk < 32; kk++) {
            float a = hs[lane * 33 + kk];
            ull aa;
            asm("mov.b64 %0, {%1, %1};" : "=l"(aa) : "f"(a));
            ulonglong2 wv = *(const ulonglong2*)(wrow + kk * COLS);  // LDS.128 broadcast
            acc0 = fma2(aa, wv.x, acc0);
            acc1 = fma2(aa, wv.y, acc1);
        }
    }

    float x0, x1, x2, x3;
    asm("mov.b64 {%0, %1}, %2;" : "=f"(x0), "=f"(x1) : "l"(acc0));
    asm("mov.b64 {%0, %1}, %2;" : "=f"(x2), "=f"(x3) : "l"(acc1));
    int c = w << 2;
    float4 o;
    o.x = tanhf(x0 + bs[c + 0]);
    o.y = tanhf(x1 + bs[c + 1]);
    o.z = tanhf(x2 + bs[c + 2]);
    o.w = tanhf(x3 + bs[c + 3]);
    *(float4*)(dst + (size_t)(rbase + lane) * H + colbase + c) = o;
}

// ---------------------------------------------------------------------------
__global__ void __launch_bounds__(NTHREADS, 1)
rnn_kernel(const float* __restrict__ cat_seq, const float* __restrict__ val_seq,
           const float* __restrict__ W_ih0, const float* __restrict__ W_hh0,
           const float* __restrict__ b0,
           const float* __restrict__ W_ih1, const float* __restrict__ W_hh1,
           const float* __restrict__ b1,
           const float* __restrict__ Wc, const float* __restrict__ bc,
           const float* __restrict__ Wm, const float* __restrict__ bm,
           float* __restrict__ out)
{
    extern __shared__ float sm[];
    float* W0s = sm + OFF_W0;
    float* W1s = sm + OFF_W1;
    float* hs  = sm + OFF_HS;
    float* bs0 = sm + OFF_B0;
    float* bs1 = sm + OFF_B1;
    float* Wms = sm + OFF_WM;
    float* Wcs = sm + OFF_WC;
    float* slg = sm + OFF_LG;

    const int tid = threadIdx.x;
    const int cta = blockIdx.x;
    const int ri  = cta >> 4;       // 0..7  (row slice, 32 rows)
    const int cj  = cta & 15;       // 0..15 (column slice, 32 cols)
    const int rbase   = ri * 32;
    const int colbase = cj * 32;

    // ---- per-launch state init (deterministic across graph replays) ----
    {
        int gt = cta * NTHREADS + tid;
        for (int i = gt; i < BATCH * H; i += GRIDN * NTHREADS) {
            g_h0[0][i] = 0.f;
            g_h1[0][i] = 0.f;
        }
        for (int i = gt; i < BATCH * NX; i += GRIDN * NTHREADS) {
            int r = i / NX, j = i - r * NX;
            g_X[i] = (j < NC) ? cat_seq[r * NC + j] : val_seq[r * NM + (j - NC)];
        }
    }

    // ---- load resident weight slices into SMEM (once) ----
    for (int idx = tid; idx < KA_PAD * COLS; idx += NTHREADS) {
        int k = idx >> 5, c = idx & 31;
        float v = 0.f;
        if (k < NX)      v = W_ih0[k * H + colbase + c];
        else if (k < KA) v = W_hh0[(k - NX) * H + colbase + c];
        W0s[idx] = v;
    }
    for (int idx = tid; idx < KB * COLS; idx += NTHREADS) {
        int k = idx >> 5, c = idx & 31;
        float v = (k < H) ? W_ih1[k * H + colbase + c]
                          : W_hh1[(k - H) * H + colbase + c];
        W1s[idx] = v;
    }
    if (tid < 32) { bs0[tid] = b0[colbase + tid]; bs1[tid] = b1[colbase + tid]; }
    for (int idx = tid; idx < 4 * H; idx += NTHREADS) {       // Wm slice, transposed
        int cc = idx >> 9, k = idx & (H - 1);
        Wms[cc * 516 + k] = Wm[k * NM + (cj << 2) + cc];
    }
    if (cj == 0) {
        for (int idx = tid; idx < 3 * H; idx += NTHREADS) {   // Wc, transposed
            int j = idx / H, k = idx - j * H;
            Wcs[j * 516 + k] = Wc[k * NC + j];
        }
    }
    gridbar();

    // ---- time loop ----
    for (int t = 0; t < T_STEPS; t++) {
        const int p = t & 1;
        const float* H0r = g_h0[p];     float* H0w = g_h0[p ^ 1];
        const float* H1r = g_h1[p];     float* H1w = g_h1[p ^ 1];

        // Phase A: h0 = tanh([X | h0_prev] @ W0 + b0)
        mm_phase(g_X, NX, NX, H0r, KA, NCH_A, W0s, bs0, hs, H0w, rbase, colbase);
        gridbar();

        // Phase B: h1 = tanh([h0 | h1_prev] @ W1 + b1)
        mm_phase(H0w, H, H, H1r, KB, NCH_B, W1s, bs1, hs, H1w, rbase, colbase);
        gridbar();

        // Phase C: heads, softmax, output write, NaN-imputation of next input
        float acc = 0.f;
        int r = 0, c = 0;
        if (tid < 128) {                                // o_val: 32 rows x 4 cols
            r = rbase + (tid >> 2);
            c = tid & 3;
            const float* hp = H1w + (size_t)r * H;
            const float* wp = Wms + c * 516;
#pragma unroll 8
            for (int k = 0; k < H; k += 4) {
                float4 h4 = *(const float4*)(hp + k);
                float4 w4 = *(const float4*)(wp + k);
                acc = fmaf(h4.x, w4.x, fmaf(h4.y, w4.y,
                      fmaf(h4.z, w4.z, fmaf(h4.w, w4.w, acc))));
            }
        } else if (cj == 0 && tid < 224) {              // logits: 32 rows x 3
            int t2 = tid - 128;
            int rl = t2 / 3, j = t2 - rl * 3;
            r = rbase + rl;
            const float* hp = H1w + (size_t)r * H;
            const float* wp = Wcs + j * 516;
#pragma unroll 8
            for (int k = 0; k < H; k += 4) {
                float4 h4 = *(const float4*)(hp + k);
                float4 w4 = *(const float4*)(wp + k);
                acc = fmaf(h4.x, w4.x, fmaf(h4.y, w4.y,
                      fmaf(h4.z, w4.z, fmaf(h4.w, w4.w, acc))));
            }
            slg[t2] = acc + __ldg(bc + j);
        }
        __syncthreads();
        if (tid < 128) {
            int ccol = (cj << 2) + c;
            float v   = acc + __ldg(bm + ccol) + g_X[r * NX + NC + ccol];
            float nxt = val_seq[(size_t)(t + 1) * BATCH * NM + r * NM + ccol];
            g_X[r * NX + NC + ccol] = (nxt != nxt) ? v : nxt;   // isnan
        } else if (cj == 0 && tid < 224) {
            int t2 = tid - 128;
            int rl = t2 / 3, j = t2 - rl * 3;
            float l0 = slg[rl * 3 + 0], l1 = slg[rl * 3 + 1], l2 = slg[rl * 3 + 2];
            float m  = fmaxf(l0, fmaxf(l1, l2));
            float e0 = expf(l0 - m), e1 = expf(l1 - m), e2 = expf(l2 - m);
            float s  = e0 + e1 + e2;
            float oc = ((j == 0) ? e0 : (j == 1) ? e1 : e2) / s;
            int rr = rbase + rl;
            out[(size_t)t * BATCH * NC + rr * NC + j] = oc;
            float nxt = cat_seq[(size_t)(t + 1) * BATCH * NC + rr * NC + j];
            g_X[rr * NX + j] = (nxt != nxt) ? oc : nxt;
        }
        gridbar();
    }
}

// ---------------------------------------------------------------------------
extern "C" void kernel_launch(void* const* d_in, const int* in_sizes, int n_in,
                              void* d_out, int out_size)
{
    (void)in_sizes; (void)n_in; (void)out_size;
    cudaFuncSetAttribute(rnn_kernel,
                         cudaFuncAttributeMaxDynamicSharedMemorySize, SMEM_BYTES);
    rnn_kernel<<<GRIDN, NTHREADS, SMEM_BYTES>>>(
        (const float*)d_in[0],  (const float*)d_in[1],
        (const float*)d_in[2],  (const float*)d_in[3],  (const float*)d_in[4],
        (const float*)d_in[5],  (const float*)d_in[6],  (const float*)d_in[7],
        (const float*)d_in[8],  (const float*)d_in[9],
        (const float*)d_in[10], (const float*)d_in[11],
        (float*)d_out);
}

// round 3
// speedup vs baseline: 1.1347x; 1.1347x over previous
#include <cuda_runtime.h>
#include <cstdint>

// ---------------------------------------------------------------------------
// RnnModelInterp v2: 2-layer tanh RNN, persistent kernel, 128 CTAs x 256 thr.
//   - weights SMEM-resident TRANSPOSED (k-contiguous) -> LDS.128 k-quads
//   - fma.rn.f32x2 paired along K: no pack MOVs, 8 FFMA2 / 4 LDS.128 per quad
//   - per-thread 2x2 register blocking (rows rg,rg+16 x cols cg,cg+16)
//   - activations staged in 64-k chunks with depth-2 register prefetch
//   - phase C (heads) also stages h1 via SMEM (L1 carveout is ~0)
// ---------------------------------------------------------------------------

#define GRIDN    128
#define NTHREADS 256

#define T_STEPS 199
#define BATCH   256
#define H       512
#define NC      3
#define NM      64

#define KA_PAD  640            // 128 (padded X) + 512 (h0prev)
#define KB      1024
#define NCH_A   10             // 64-k chunks
#define NCH_B   16
#define SPLIT_A 2              // chunks 0..1 from g_Xp, rest from h0prev
#define SPLIT_B 8

#define SA      644            // W0t row stride (floats), 644%32==4
#define SB      1028           // W1t row stride
#define SH      68             // hs row stride
#define SWM     516            // Wms row stride

// shared memory layout (float offsets)
#define OFF_W0  0                              // 32*644 = 20608
#define OFF_W1  (OFF_W0 + 32 * SA)             // 20608
#define OFF_HS  (OFF_W1 + 32 * SB)             // 53504
#define OFF_WM  (OFF_HS + 32 * SH)             // 55680 (4 x 516)
#define OFF_B0  (OFF_WM + 4 * SWM)             // 57744
#define OFF_B1  (OFF_B0 + 32)                  // 57776
#define OFF_LG  (OFF_B1 + 32)                  // 57808
#define SMEM_FLOATS (OFF_LG + 96)              // 57904
#define SMEM_BYTES  (SMEM_FLOATS * 4)          // 231616 <= 232448

typedef unsigned long long ull;

// persistent device state
__device__ float g_h0[2][BATCH * H];
__device__ float g_h1[2][BATCH * H];
__device__ float g_Xp[BATCH * 128];        // [cat(3) | val(64) | zeros(61)]
__device__ float g_Wct[NC * H];            // transposed Wc
__device__ ull   g_barcnt;

__device__ __forceinline__ ull fma2(ull a, ull b, ull c) {
    ull d;
    asm("fma.rn.f32x2 %0, %1, %2, %3;" : "=l"(d) : "l"(a), "l"(b), "l"(c));
    return d;
}
__device__ __forceinline__ float hadd(ull p) {
    float x, y;
    asm("mov.b64 {%0, %1}, %2;" : "=f"(x), "=f"(y) : "l"(p));
    return x + y;
}

__device__ __forceinline__ void gridbar() {
    __syncthreads();
    if (threadIdx.x == 0) {
        __threadfence();
        ull old = atomicAdd(&g_barcnt, 1ULL);
        ull target = old - (old & (ull)(GRIDN - 1)) + (ull)GRIDN;
        while (*((volatile ull*)&g_barcnt) < target) { }
        __threadfence();
    }
    __syncthreads();
}

// load one 8-float staging slice (2 float4) for chunk ch
__device__ __forceinline__ void ld_chunk(
    const float* __restrict__ srcA, int strideA, int splitCh,
    const float* __restrict__ srcB, int strideB,
    int ch, int rbase, int srow, int sinner, float4& a, float4& b)
{
    const float* p;
    if (ch < splitCh) p = srcA + (size_t)(rbase + srow) * strideA + ch * 64 + sinner;
    else              p = srcB + (size_t)(rbase + srow) * strideB + (ch - splitCh) * 64 + sinner;
    a = *(const float4*)p;
    b = *(const float4*)(p + 4);
}

// fused GEMM phase: dst[32 rows x 32 cols] = tanh(act @ Wt^T + bias)
__device__ __forceinline__ void mm_phase(
    const float* __restrict__ srcA, int strideA, int splitCh,
    const float* __restrict__ srcB, int strideB, int nch,
    const float* __restrict__ Wt, int wstride, const float* __restrict__ bs,
    float* __restrict__ hs, float* __restrict__ dst, int rbase, int colbase)
{
    const int tid = threadIdx.x;
    const int w = tid >> 5, l = tid & 31;
    const int rg = ((w >> 1) << 2) | (l >> 3);     // 0..15
    const int cg = ((w & 1) << 3) | (l & 7);       // 0..15
    const int srow = tid >> 3, sinner = (tid & 7) << 3;

    const float* hr0 = hs + rg * SH;
    const float* hr1 = hs + (rg + 16) * SH;
    const float* wc0 = Wt + cg * wstride;
    const float* wc1 = Wt + (cg + 16) * wstride;

    float4 a0, b0, a1, b1;
    ld_chunk(srcA, strideA, splitCh, srcB, strideB, 0, rbase, srow, sinner, a0, b0);
    ld_chunk(srcA, strideA, splitCh, srcB, strideB, 1, rbase, srow, sinner, a1, b1);

    ull e00 = 0, o00 = 0, e01 = 0, o01 = 0, e10 = 0, o10 = 0, e11 = 0, o11 = 0;
    for (int ch = 0; ch < nch; ch++) {
        __syncthreads();
        *(float4*)(hs + srow * SH + sinner)     = a0;
        *(float4*)(hs + srow * SH + sinner + 4) = b0;
        __syncthreads();
        a0 = a1; b0 = b1;
        if (ch + 2 < nch)
            ld_chunk(srcA, strideA, splitCh, srcB, strideB, ch + 2, rbase, srow, sinner, a1, b1);
        const float* wp0 = wc0 + ch * 64;
        const float* wp1 = wc1 + ch * 64;
#pragma unroll
        for (int q = 0; q < 16; q++) {
            ulonglong2 x0 = *(const ulonglong2*)(hr0 + (q << 2));
            ulonglong2 x1 = *(const ulonglong2*)(hr1 + (q << 2));
            ulonglong2 y0 = *(const ulonglong2*)(wp0 + (q << 2));
            ulonglong2 y1 = *(const ulonglong2*)(wp1 + (q << 2));
            e00 = fma2(x0.x, y0.x, e00);  o00 = fma2(x0.y, y0.y, o00);
            e01 = fma2(x0.x, y1.x, e01);  o01 = fma2(x0.y, y1.y, o01);
            e10 = fma2(x1.x, y0.x, e10);  o10 = fma2(x1.y, y0.y, o10);
            e11 = fma2(x1.x, y1.x, e11);  o11 = fma2(x1.y, y1.y, o11);
        }
    }
    float s00 = hadd(e00) + hadd(o00);
    float s01 = hadd(e01) + hadd(o01);
    float s10 = hadd(e10) + hadd(o10);
    float s11 = hadd(e11) + hadd(o11);
    const int r0 = rbase + rg, r1 = rbase + rg + 16;
    const int c0 = colbase + cg, c1 = colbase + cg + 16;
    dst[(size_t)r0 * H + c0] = tanhf(s00 + bs[cg]);
    dst[(size_t)r0 * H + c1] = tanhf(s01 + bs[cg + 16]);
    dst[(size_t)r1 * H + c0] = tanhf(s10 + bs[cg]);
    dst[(size_t)r1 * H + c1] = tanhf(s11 + bs[cg + 16]);
}

// ---------------------------------------------------------------------------
__global__ void __launch_bounds__(NTHREADS, 1)
rnn_kernel(const float* __restrict__ cat_seq, const float* __restrict__ val_seq,
           const float* __restrict__ W_ih0, const float* __restrict__ W_hh0,
           const float* __restrict__ b0,
           const float* __restrict__ W_ih1, const float* __restrict__ W_hh1,
           const float* __restrict__ b1,
           const float* __restrict__ Wc, const float* __restrict__ bc,
           const float* __restrict__ Wm, const float* __restrict__ bm,
           float* __restrict__ out)
{
    extern __shared__ float sm[];
    float* W0s = sm + OFF_W0;
    float* W1s = sm + OFF_W1;
    float* hs  = sm + OFF_HS;
    float* Wms = sm + OFF_WM;
    float* bs0 = sm + OFF_B0;
    float* bs1 = sm + OFF_B1;
    float* slg = sm + OFF_LG;

    const int tid = threadIdx.x;
    const int cta = blockIdx.x;
    const int ri  = cta >> 4;
    const int cj  = cta & 15;
    const int rbase   = ri * 32;
    const int colbase = cj * 32;

    // ---- per-launch init ----
    {
        int gt = cta * NTHREADS + tid;
        for (int i = gt; i < BATCH * H; i += GRIDN * NTHREADS) {
            g_h0[0][i] = 0.f;
            g_h1[0][i] = 0.f;
        }
        for (int i = gt; i < BATCH * 128; i += GRIDN * NTHREADS) {
            int r = i >> 7, s = i & 127;
            float v = 0.f;
            if (s < NC)           v = cat_seq[r * NC + s];
            else if (s < NC + NM) v = val_seq[r * NM + (s - NC)];
            g_Xp[i] = v;
        }
        for (int i = gt; i < NC * H; i += GRIDN * NTHREADS) {
            int j = i >> 9, k = i & (H - 1);
            g_Wct[i] = Wc[k * NC + j];          // g_Wct[j*512+k]
        }
    }

    // ---- SMEM weight slices (transposed, k-contiguous) ----
    for (int idx = tid; idx < 32 * SA; idx += NTHREADS) {
        int c = idx / SA, k = idx - c * SA;
        float v = 0.f;
        if (k < NC + NM)              v = W_ih0[k * H + colbase + c];
        else if (k >= 128 && k < 640) v = W_hh0[(k - 128) * H + colbase + c];
        W0s[idx] = v;
    }
    for (int idx = tid; idx < 32 * SB; idx += NTHREADS) {
        int c = idx / SB, k = idx - c * SB;
        float v = 0.f;
        if (k < H)         v = W_ih1[k * H + colbase + c];
        else if (k < 2*H)  v = W_hh1[(k - H) * H + colbase + c];
        W1s[idx] = v;
    }
    if (tid < 32) { bs0[tid] = b0[colbase + tid]; bs1[tid] = b1[colbase + tid]; }
    for (int idx = tid; idx < 4 * H; idx += NTHREADS) {     // Wm slice transposed
        int c = idx >> 9, k = idx & (H - 1);
        Wms[c * SWM + k] = Wm[k * NM + (cj << 2) + c];
    }
    gridbar();

    // phase-C thread roles
    const int vr = tid >> 2, vc = tid & 3;              // val head (tid<128)
    const int t2 = tid - 128;
    const int rl = (t2 >= 0) ? t2 / 3 : 0, jj = (t2 >= 0) ? t2 - rl * 3 : 0;
    const int srow = tid >> 3, sinner = (tid & 7) << 3;

    // ---- time loop ----
    for (int t = 0; t < T_STEPS; t++) {
        const int p = t & 1;
        const float* H0r = g_h0[p];   float* H0w = g_h0[p ^ 1];
        const float* H1r = g_h1[p];   float* H1w = g_h1[p ^ 1];

        // Phase A
        mm_phase(g_Xp, 128, SPLIT_A, H0r, H, NCH_A, W0s, SA, bs0, hs, H0w, rbase, colbase);
        gridbar();

        // Phase B
        mm_phase(H0w, H, SPLIT_B, H1r, H, NCH_B, W1s, SB, bs1, hs, H1w, rbase, colbase);
        gridbar();

        // Phase C: stage h1 rows chunk-wise through SMEM; heads + softmax + impute
        {
            float acc = 0.f;
            float4 a0, b0, a1, b1;
            ld_chunk(H1w, H, 8, H1w, H, 0, rbase, srow, sinner, a0, b0);
            ld_chunk(H1w, H, 8, H1w, H, 1, rbase, srow, sinner, a1, b1);
            for (int ch = 0; ch < 8; ch++) {
                __syncthreads();
                *(float4*)(hs + srow * SH + sinner)     = a0;
                *(float4*)(hs + srow * SH + sinner + 4) = b0;
                __syncthreads();
                a0 = a1; b0 = b1;
                if (ch + 2 < 8)
                    ld_chunk(H1w, H, 8, H1w, H, ch + 2, rbase, srow, sinner, a1, b1);
                if (tid < 128) {
                    const float* hp = hs + vr * SH;
                    const float* wp = Wms + vc * SWM + ch * 64;
#pragma unroll
                    for (int q = 0; q < 16; q++) {
                        float4 h4 = *(const float4*)(hp + (q << 2));
                        float4 w4 = *(const float4*)(wp + (q << 2));
                        acc = fmaf(h4.x, w4.x, fmaf(h4.y, w4.y,
                              fmaf(h4.z, w4.z, fmaf(h4.w, w4.w, acc))));
                    }
                } else if (cj == 0 && tid < 224) {
                    const float* hp = hs + rl * SH;
                    const float* wp = g_Wct + jj * H + ch * 64;
#pragma unroll
                    for (int q = 0; q < 16; q++) {
                        float4 h4 = *(const float4*)(hp + (q << 2));
                        float4 w4 = *(const float4*)(wp + (q << 2));
                        acc = fmaf(h4.x, w4.x, fmaf(h4.y, w4.y,
                              fmaf(h4.z, w4.z, fmaf(h4.w, w4.w, acc))));
                    }
                }
            }
            if (cj == 0 && tid >= 128 && tid < 224)
                slg[t2] = acc + __ldg(bc + jj);
            __syncthreads();
            if (tid < 128) {
                int ccol = (cj << 2) + vc;
                int r = rbase + vr;
                float v   = acc + __ldg(bm + ccol) + g_Xp[r * 128 + NC + ccol];
                float nxt = val_seq[(size_t)(t + 1) * BATCH * NM + r * NM + ccol];
                g_Xp[r * 128 + NC + ccol] = (nxt != nxt) ? v : nxt;
            } else if (cj == 0 && tid < 224) {
                float l0 = slg[rl * 3 + 0], l1 = slg[rl * 3 + 1], l2 = slg[rl * 3 + 2];
                float m  = fmaxf(l0, fmaxf(l1, l2));
                float e0 = expf(l0 - m), e1 = expf(l1 - m), e2 = expf(l2 - m);
                float s  = e0 + e1 + e2;
                float oc = ((jj == 0) ? e0 : (jj == 1) ? e1 : e2) / s;
                int r = rbase + rl;
                out[(size_t)t * BATCH * NC + r * NC + jj] = oc;
                float nxt = cat_seq[(size_t)(t + 1) * BATCH * NC + r * NC + jj];
                g_Xp[r * 128 + jj] = (nxt != nxt) ? oc : nxt;
            }
        }
        gridbar();
    }
}

// ---------------------------------------------------------------------------
extern "C" void kernel_launch(void* const* d_in, const int* in_sizes, int n_in,
                              void* d_out, int out_size)
{
    (void)in_sizes; (void)n_in; (void)out_size;
    cudaFuncSetAttribute(rnn_kernel,
                         cudaFuncAttributeMaxDynamicSharedMemorySize, SMEM_BYTES);
    rnn_kernel<<<GRIDN, NTHREADS, SMEM_BYTES>>>(
        (const float*)d_in[0],  (const float*)d_in[1],
        (const float*)d_in[2],  (const float*)d_in[3],  (const float*)d_in[4],
        (const float*)d_in[5],  (const float*)d_in[6],  (const float*)d_in[7],
        (const float*)d_in[8],  (const float*)d_in[9],
        (const float*)d_in[10], (const float*)d_in[11],
        (float*)d_out);
}

// round 5
// speedup vs baseline: 1.1661x; 1.0277x over previous
#include <cuda_runtime.h>
#include <cstdint>

// ---------------------------------------------------------------------------
// RnnModelInterp v3b: persistent kernel, 128 CTAs x 256 thr.
//   v2 + (a) acq/rel grid barrier (no membar.gpu / no CCTL.IVALL L1 flush)
//        (b) chunk-reordered GEMM phases with cross-barrier prefetch of the
//            stable (recurrent) activation half
//        (c) defensive nanosleep backoff in the barrier spin (infra hardening)
// ---------------------------------------------------------------------------

#define GRIDN    128
#define NTHREADS 256

#define T_STEPS 199
#define BATCH   256
#define H       512
#define NC      3
#define NM      64

#define NCH_A   10             // 64-k chunks (128 padded X + 512 h0prev)
#define NCH_B   16             // (512 h0 + 512 h1prev)
#define SPLIT_A 2              // chunks 0..1 from g_Xp, rest from h0prev
#define SPLIT_B 8
#define START_A 2              // begin with stable h0prev chunks
#define START_B 8              // begin with stable h1prev chunks

#define SA      644            // W0t row stride (floats)
#define SB      1028           // W1t row stride
#define SH      68             // hs row stride
#define SWM     516            // Wms row stride

#define OFF_W0  0
#define OFF_W1  (OFF_W0 + 32 * SA)
#define OFF_HS  (OFF_W1 + 32 * SB)
#define OFF_WM  (OFF_HS + 32 * SH)
#define OFF_B0  (OFF_WM + 4 * SWM)
#define OFF_B1  (OFF_B0 + 32)
#define OFF_LG  (OFF_B1 + 32)
#define SMEM_FLOATS (OFF_LG + 96)
#define SMEM_BYTES  (SMEM_FLOATS * 4)          // 231616 <= 232448

typedef unsigned long long ull;

__device__ float g_h0[2][BATCH * H];
__device__ float g_h1[2][BATCH * H];
__device__ float g_Xp[BATCH * 128];        // [cat(3) | val(64) | zeros(61)]
__device__ float g_Wct[NC * H];
__device__ ull   g_barcnt;

__device__ __forceinline__ ull fma2(ull a, ull b, ull c) {
    ull d;
    asm("fma.rn.f32x2 %0, %1, %2, %3;" : "=l"(d) : "l"(a), "l"(b), "l"(c));
    return d;
}
__device__ __forceinline__ float hadd(ull p) {
    float x, y;
    asm("mov.b64 {%0, %1}, %2;" : "=f"(x), "=f"(y) : "l"(p));
    return x + y;
}

// grid barrier: release-atomic arrival + acquire-load spin. No threadfence,
// no L1 flush. Replay-safe: target derived from this CTA's own fetch-add.
__device__ __forceinline__ void gridbar() {
    __syncthreads();
    if (threadIdx.x == 0) {
        ull old;
        asm volatile("atom.release.gpu.global.add.u64 %0, [%1], 1;"
                     : "=l"(old) : "l"(&g_barcnt) : "memory");
        ull target = old - (old & (ull)(GRIDN - 1)) + (ull)GRIDN;
        ull v;
        int polls = 0;
        for (;;) {
            asm volatile("ld.acquire.gpu.global.u64 %0, [%1];"
                         : "=l"(v) : "l"(&g_barcnt) : "memory");
            if (v >= target) break;
            if (++polls > 4096) __nanosleep(64);   // defensive backoff only
        }
    }
    __syncthreads();
}

// load one 8-float staging slice (2 float4) for chunk ch
__device__ __forceinline__ void ld_chunk(
    const float* __restrict__ srcA, int strideA, int splitCh,
    const float* __restrict__ srcB, int strideB,
    int ch, int rbase, int srow, int sinner, float4& a, float4& b)
{
    const float* p;
    if (ch < splitCh) p = srcA + (size_t)(rbase + srow) * strideA + ch * 64 + sinner;
    else              p = srcB + (size_t)(rbase + srow) * strideB + (ch - splitCh) * 64 + sinner;
    a = *(const float4*)p;
    b = *(const float4*)(p + 4);
}

// fused GEMM phase, chunk order start, start+1, ..., wrap. Chunks (start,
// start+1) arrive preloaded in (a0,b0,a1,b1) -- caller may issue those loads
// BEFORE the preceding grid barrier when they come from stable buffers.
__device__ __forceinline__ void mm_phase(
    const float* __restrict__ srcA, int strideA, int splitCh,
    const float* __restrict__ srcB, int strideB, int nch, int start,
    float4 a0, float4 b0, float4 a1, float4 b1,
    const float* __restrict__ Wt, int wstride, const float* __restrict__ bs,
    float* __restrict__ hs, float* __restrict__ dst, int rbase, int colbase)
{
    const int tid = threadIdx.x;
    const int w = tid >> 5, l = tid & 31;
    const int rg = ((w >> 1) << 2) | (l >> 3);     // 0..15
    const int cg = ((w & 1) << 3) | (l & 7);       // 0..15
    const int srow = tid >> 3, sinner = (tid & 7) << 3;

    const float* hr0 = hs + rg * SH;
    const float* hr1 = hs + (rg + 16) * SH;
    const float* wc0 = Wt + cg * wstride;
    const float* wc1 = Wt + (cg + 16) * wstride;

    ull e00 = 0, o00 = 0, e01 = 0, o01 = 0, e10 = 0, o10 = 0, e11 = 0, o11 = 0;
    for (int i = 0; i < nch; i++) {
        int ch = start + i; if (ch >= nch) ch -= nch;
        __syncthreads();
        *(float4*)(hs + srow * SH + sinner)     = a0;
        *(float4*)(hs + srow * SH + sinner + 4) = b0;
        __syncthreads();
        a0 = a1; b0 = b1;
        if (i + 2 < nch) {
            int ch2 = start + i + 2; if (ch2 >= nch) ch2 -= nch;
            ld_chunk(srcA, strideA, splitCh, srcB, strideB, ch2, rbase, srow, sinner, a1, b1);
        }
        const float* wp0 = wc0 + ch * 64;
        const float* wp1 = wc1 + ch * 64;
#pragma unroll
        for (int q = 0; q < 16; q++) {
            ulonglong2 x0 = *(const ulonglong2*)(hr0 + (q << 2));
            ulonglong2 x1 = *(const ulonglong2*)(hr1 + (q << 2));
            ulonglong2 y0 = *(const ulonglong2*)(wp0 + (q << 2));
            ulonglong2 y1 = *(const ulonglong2*)(wp1 + (q << 2));
            e00 = fma2(x0.x, y0.x, e00);  o00 = fma2(x0.y, y0.y, o00);
            e01 = fma2(x0.x, y1.x, e01);  o01 = fma2(x0.y, y1.y, o01);
            e10 = fma2(x1.x, y0.x, e10);  o10 = fma2(x1.y, y0.y, o10);
            e11 = fma2(x1.x, y1.x, e11);  o11 = fma2(x1.y, y1.y, o11);
        }
    }
    float s00 = hadd(e00) + hadd(o00);
    float s01 = hadd(e01) + hadd(o01);
    float s10 = hadd(e10) + hadd(o10);
    float s11 = hadd(e11) + hadd(o11);
    const int r0 = rbase + rg, r1 = rbase + rg + 16;
    const int c0 = colbase + cg, c1 = colbase + cg + 16;
    dst[(size_t)r0 * H + c0] = tanhf(s00 + bs[cg]);
    dst[(size_t)r0 * H + c1] = tanhf(s01 + bs[cg + 16]);
    dst[(size_t)r1 * H + c0] = tanhf(s10 + bs[cg]);
    dst[(size_t)r1 * H + c1] = tanhf(s11 + bs[cg + 16]);
}

// ---------------------------------------------------------------------------
__global__ void __launch_bounds__(NTHREADS, 1)
rnn_kernel(const float* __restrict__ cat_seq, const float* __restrict__ val_seq,
           const float* __restrict__ W_ih0, const float* __restrict__ W_hh0,
           const float* __restrict__ b0,
           const float* __restrict__ W_ih1, const float* __restrict__ W_hh1,
           const float* __restrict__ b1,
           const float* __restrict__ Wc, const float* __restrict__ bc,
           const float* __restrict__ Wm, const float* __restrict__ bm,
           float* __restrict__ out)
{
    extern __shared__ float sm[];
    float* W0s = sm + OFF_W0;
    float* W1s = sm + OFF_W1;
    float* hs  = sm + OFF_HS;
    float* Wms = sm + OFF_WM;
    float* bs0 = sm + OFF_B0;
    float* bs1 = sm + OFF_B1;
    float* slg = sm + OFF_LG;

    const int tid = threadIdx.x;
    const int cta = blockIdx.x;
    const int ri  = cta >> 4;
    const int cj  = cta & 15;
    const int rbase   = ri * 32;
    const int colbase = cj * 32;

    // ---- per-launch init ----
    {
        int gt = cta * NTHREADS + tid;
        for (int i = gt; i < BATCH * H; i += GRIDN * NTHREADS) {
            g_h0[0][i] = 0.f;
            g_h1[0][i] = 0.f;
        }
        for (int i = gt; i < BATCH * 128; i += GRIDN * NTHREADS) {
            int r = i >> 7, s = i & 127;
            float v = 0.f;
            if (s < NC)           v = cat_seq[r * NC + s];
            else if (s < NC + NM) v = val_seq[r * NM + (s - NC)];
            g_Xp[i] = v;
        }
        for (int i = gt; i < NC * H; i += GRIDN * NTHREADS) {
            int j = i >> 9, k = i & (H - 1);
            g_Wct[i] = Wc[k * NC + j];
        }
    }

    // ---- SMEM weight slices (transposed, k-contiguous) ----
    for (int idx = tid; idx < 32 * SA; idx += NTHREADS) {
        int c = idx / SA, k = idx - c * SA;
        float v = 0.f;
        if (k < NC + NM)              v = W_ih0[k * H + colbase + c];
        else if (k >= 128 && k < 640) v = W_hh0[(k - 128) * H + colbase + c];
        W0s[idx] = v;
    }
    for (int idx = tid; idx < 32 * SB; idx += NTHREADS) {
        int c = idx / SB, k = idx - c * SB;
        float v = 0.f;
        if (k < H)         v = W_ih1[k * H + colbase + c];
        else if (k < 2*H)  v = W_hh1[(k - H) * H + colbase + c];
        W1s[idx] = v;
    }
    if (tid < 32) { bs0[tid] = b0[colbase + tid]; bs1[tid] = b1[colbase + tid]; }
    for (int idx = tid; idx < 4 * H; idx += NTHREADS) {
        int c = idx >> 9, k = idx & (H - 1);
        Wms[c * SWM + k] = Wm[k * NM + (cj << 2) + c];
    }
    gridbar();

    const int vr = tid >> 2, vc = tid & 3;
    const int t2 = tid - 128;
    const int rl = (t2 >= 0) ? t2 / 3 : 0, jj = (t2 >= 0) ? t2 - rl * 3 : 0;
    const int srow = tid >> 3, sinner = (tid & 7) << 3;

    // preload phase-A chunks (START_A, START_A+1) for t=0 (post-init-barrier)
    float4 pAa0, pAb0, pAa1, pAb1;
    ld_chunk(g_Xp, 128, SPLIT_A, g_h0[0], H, START_A,     rbase, srow, sinner, pAa0, pAb0);
    ld_chunk(g_Xp, 128, SPLIT_A, g_h0[0], H, START_A + 1, rbase, srow, sinner, pAa1, pAb1);

    // ---- time loop ----
    for (int t = 0; t < T_STEPS; t++) {
        const int p = t & 1;
        const float* H0r = g_h0[p];   float* H0w = g_h0[p ^ 1];
        const float* H1r = g_h1[p];   float* H1w = g_h1[p ^ 1];

        // Phase A (starts at stable h0prev chunks; preloaded pre-barrier)
        mm_phase(g_Xp, 128, SPLIT_A, H0r, H, NCH_A, START_A,
                 pAa0, pAb0, pAa1, pAb1, W0s, SA, bs0, hs, H0w, rbase, colbase);

        // preload phase-B chunks from H1r (stable since previous step) BEFORE bar
        float4 pBa0, pBb0, pBa1, pBb1;
        ld_chunk(H0w, H, SPLIT_B, H1r, H, START_B,     rbase, srow, sinner, pBa0, pBb0);
        ld_chunk(H0w, H, SPLIT_B, H1r, H, START_B + 1, rbase, srow, sinner, pBa1, pBb1);
        gridbar();

        // Phase B
        mm_phase(H0w, H, SPLIT_B, H1r, H, NCH_B, START_B,
                 pBa0, pBb0, pBa1, pBb1, W1s, SB, bs1, hs, H1w, rbase, colbase);
        gridbar();

        // Phase C
        {
            float acc = 0.f;
            float4 a0, b0, a1, b1;
            ld_chunk(H1w, H, 8, H1w, H, 0, rbase, srow, sinner, a0, b0);
            ld_chunk(H1w, H, 8, H1w, H, 1, rbase, srow, sinner, a1, b1);
            for (int ch = 0; ch < 8; ch++) {
                __syncthreads();
                *(float4*)(hs + srow * SH + sinner)     = a0;
                *(float4*)(hs + srow * SH + sinner + 4) = b0;
                __syncthreads();
                a0 = a1; b0 = b1;
                if (ch + 2 < 8)
                    ld_chunk(H1w, H, 8, H1w, H, ch + 2, rbase, srow, sinner, a1, b1);
                if (tid < 128) {
                    const float* hp = hs + vr * SH;
                    const float* wp = Wms + vc * SWM + ch * 64;
#pragma unroll
                    for (int q = 0; q < 16; q++) {
                        float4 h4 = *(const float4*)(hp + (q << 2));
                        float4 w4 = *(const float4*)(wp + (q << 2));
                        acc = fmaf(h4.x, w4.x, fmaf(h4.y, w4.y,
                              fmaf(h4.z, w4.z, fmaf(h4.w, w4.w, acc))));
                    }
                } else if (cj == 0 && tid < 224) {
                    const float* hp = hs + rl * SH;
                    const float* wp = g_Wct + jj * H + ch * 64;
#pragma unroll
                    for (int q = 0; q < 16; q++) {
                        float4 h4 = *(const float4*)(hp + (q << 2));
                        float4 w4 = *(const float4*)(wp + (q << 2));
                        acc = fmaf(h4.x, w4.x, fmaf(h4.y, w4.y,
                              fmaf(h4.z, w4.z, fmaf(h4.w, w4.w, acc))));
                    }
                }
            }
            if (cj == 0 && tid >= 128 && tid < 224)
                slg[t2] = acc + __ldg(bc + jj);
            __syncthreads();
            if (tid < 128) {
                int ccol = (cj << 2) + vc;
                int r = rbase + vr;
                float v   = acc + __ldg(bm + ccol) + g_Xp[r * 128 + NC + ccol];
                float nxt = val_seq[(size_t)(t + 1) * BATCH * NM + r * NM + ccol];
                g_Xp[r * 128 + NC + ccol] = (nxt != nxt) ? v : nxt;
            } else if (cj == 0 && tid < 224) {
                float l0 = slg[rl * 3 + 0], l1 = slg[rl * 3 + 1], l2 = slg[rl * 3 + 2];
                float m  = fmaxf(l0, fmaxf(l1, l2));
                float e0 = expf(l0 - m), e1 = expf(l1 - m), e2 = expf(l2 - m);
                float s  = e0 + e1 + e2;
                float oc = ((jj == 0) ? e0 : (jj == 1) ? e1 : e2) / s;
                int r = rbase + rl;
                out[(size_t)t * BATCH * NC + r * NC + jj] = oc;
                float nxt = cat_seq[(size_t)(t + 1) * BATCH * NC + r * NC + jj];
                g_Xp[r * 128 + jj] = (nxt != nxt) ? oc : nxt;
            }
        }
        // preload next step's phase-A chunks from H0w (stable; written in A above)
        if (t + 1 < T_STEPS) {
            ld_chunk(g_Xp, 128, SPLIT_A, H0w, H, START_A,     rbase, srow, sinner, pAa0, pAb0);
            ld_chunk(g_Xp, 128, SPLIT_A, H0w, H, START_A + 1, rbase, srow, sinner, pAa1, pAb1);
        }
        gridbar();
    }
}

// ---------------------------------------------------------------------------
extern "C" void kernel_launch(void* const* d_in, const int* in_sizes, int n_in,
                              void* d_out, int out_size)
{
    (void)in_sizes; (void)n_in; (void)out_size;
    cudaFuncSetAttribute(rnn_kernel,
                         cudaFuncAttributeMaxDynamicSharedMemorySize, SMEM_BYTES);
    rnn_kernel<<<GRIDN, NTHREADS, SMEM_BYTES>>>(
        (const float*)d_in[0],  (const float*)d_in[1],
        (const float*)d_in[2],  (const float*)d_in[3],  (const float*)d_in[4],
        (const float*)d_in[5],  (const float*)d_in[6],  (const float*)d_in[7],
        (const float*)d_in[8],  (const float*)d_in[9],
        (const float*)d_in[10], (const float*)d_in[11],
        (float*)d_out);
}

// round 7
// speedup vs baseline: 2.0520x; 1.7597x over previous
#include <cuda_runtime.h>
#include <cstdint>

// ---------------------------------------------------------------------------
// RnnModelInterp v4b: persistent kernel, 128 CTAs x 256 thr.
//   tf32 tensor-core GEMM phases (mma.sync.m16n8k8):
//     - 8 warps = 2x2 warp-tiles (16x16) x 2 K-halves per 64-k chunk
//     - all fragment loads conflict-free LDS.32
//     - K-half partials reduced through SMEM in epilogue (+bias+tanh)
//   v4 fix: epilogue scratch row stride 33 -> 34 (odd stride made float2
//   SMEM accesses 4-byte aligned -> misaligned-address trap).
// ---------------------------------------------------------------------------

#define GRIDN    128
#define NTHREADS 256

#define T_STEPS 199
#define BATCH   256
#define H       512
#define NC      3
#define NM      64

#define NCH_A   10             // 64-k chunks (128 padded X + 512 h0prev)
#define NCH_B   16             // (512 h0 + 512 h1prev)
#define SPLIT_A 2
#define SPLIT_B 8
#define START_A 2              // begin with stable h0prev chunks
#define START_B 8              // begin with stable h1prev chunks

#define SA      644            // W0t row stride (floats)
#define SB      1028           // W1t row stride
#define SH      68             // staging row stride
#define SE      34             // epilogue scratch row stride (EVEN: float2-safe)
#define SWM     516            // Wms row stride

#define OFF_W0  0
#define OFF_W1  (OFF_W0 + 32 * SA)
#define OFF_HS  (OFF_W1 + 32 * SB)
#define OFF_WM  (OFF_HS + 32 * SH)
#define OFF_B0  (OFF_WM + 4 * SWM)
#define OFF_B1  (OFF_B0 + 32)
#define OFF_LG  (OFF_B1 + 32)
#define SMEM_FLOATS (OFF_LG + 96)
#define SMEM_BYTES  (SMEM_FLOATS * 4)          // 231616 <= 232448

typedef unsigned long long ull;

__device__ float g_h0[2][BATCH * H];
__device__ float g_h1[2][BATCH * H];
__device__ float g_Xp[BATCH * 128];        // [cat(3) | val(64) | zeros(61)]
__device__ float g_Wct[NC * H];
__device__ ull   g_barcnt;

__device__ __forceinline__ uint32_t tf32r(float f) {
    uint32_t u;
    asm("cvt.rna.tf32.f32 %0, %1;" : "=r"(u) : "f"(f));
    return u;
}

__device__ __forceinline__ void mma8(float* c,
    uint32_t a0, uint32_t a1, uint32_t a2, uint32_t a3,
    uint32_t b0, uint32_t b1)
{
    asm volatile("mma.sync.aligned.m16n8k8.row.col.f32.tf32.tf32.f32 "
        "{%0,%1,%2,%3}, {%4,%5,%6,%7}, {%8,%9}, {%0,%1,%2,%3};"
        : "+f"(c[0]), "+f"(c[1]), "+f"(c[2]), "+f"(c[3])
        : "r"(a0), "r"(a1), "r"(a2), "r"(a3), "r"(b0), "r"(b1));
}

// grid barrier: release-atomic arrival + acquire-load spin; replay-safe.
__device__ __forceinline__ void gridbar() {
    __syncthreads();
    if (threadIdx.x == 0) {
        ull old;
        asm volatile("atom.release.gpu.global.add.u64 %0, [%1], 1;"
                     : "=l"(old) : "l"(&g_barcnt) : "memory");
        ull target = old - (old & (ull)(GRIDN - 1)) + (ull)GRIDN;
        ull v;
        int polls = 0;
        for (;;) {
            asm volatile("ld.acquire.gpu.global.u64 %0, [%1];"
                         : "=l"(v) : "l"(&g_barcnt) : "memory");
            if (v >= target) break;
            if (++polls > 4096) __nanosleep(64);
        }
    }
    __syncthreads();
}

// load one 8-float staging slice (2 float4) for chunk ch
__device__ __forceinline__ void ld_chunk(
    const float* __restrict__ srcA, int strideA, int splitCh,
    const float* __restrict__ srcB, int strideB,
    int ch, int rbase, int srow, int sinner, float4& a, float4& b)
{
    const float* p;
    if (ch < splitCh) p = srcA + (size_t)(rbase + srow) * strideA + ch * 64 + sinner;
    else              p = srcB + (size_t)(rbase + srow) * strideB + (ch - splitCh) * 64 + sinner;
    a = *(const float4*)p;
    b = *(const float4*)(p + 4);
}

// tf32 tensor-core GEMM phase: dst[32 rows x 32 cols] = tanh(act @ Wt^T + b).
// Warp w: kh=w>>2 (K-half within each 64-chunk), wr=(w>>1)&1, wc=w&1.
__device__ __forceinline__ void mm_phase(
    const float* __restrict__ srcA, int strideA, int splitCh,
    const float* __restrict__ srcB, int strideB, int nch, int start,
    float4 a0, float4 b0, float4 a1, float4 b1,
    const float* __restrict__ Wt, int wstride, const float* __restrict__ bs,
    float* __restrict__ hs, float* __restrict__ dst, int rbase, int colbase)
{
    const int tid = threadIdx.x;
    const int w = tid >> 5, lane = tid & 31;
    const int g = lane >> 2, tig = lane & 3;
    const int kh = w >> 2, wr = (w >> 1) & 1, wc = w & 1;
    const int srow = tid >> 3, sinner = (tid & 7) << 3;

    float acc[8];
#pragma unroll
    for (int i = 0; i < 8; i++) acc[i] = 0.f;

    const int ar0 = (wr * 16 + g) * SH;
    const int ar1 = (wr * 16 + g + 8) * SH;
    const float* wn0 = Wt + (wc * 16 + g) * wstride;        // n-tile 0 col g
    const float* wn1 = Wt + (wc * 16 + 8 + g) * wstride;    // n-tile 1 col g
    const int kk = kh * 32;

    for (int i = 0; i < nch; i++) {
        int ch = start + i; if (ch >= nch) ch -= nch;
        __syncthreads();
        {   // staging store with tf32 rounding
            float* sp = hs + srow * SH + sinner;
            sp[0] = __uint_as_float(tf32r(a0.x));
            sp[1] = __uint_as_float(tf32r(a0.y));
            sp[2] = __uint_as_float(tf32r(a0.z));
            sp[3] = __uint_as_float(tf32r(a0.w));
            sp[4] = __uint_as_float(tf32r(b0.x));
            sp[5] = __uint_as_float(tf32r(b0.y));
            sp[6] = __uint_as_float(tf32r(b0.z));
            sp[7] = __uint_as_float(tf32r(b0.w));
        }
        __syncthreads();
        a0 = a1; b0 = b1;
        if (i + 2 < nch) {
            int ch2 = start + i + 2; if (ch2 >= nch) ch2 -= nch;
            ld_chunk(srcA, strideA, splitCh, srcB, strideB, ch2, rbase, srow, sinner, a1, b1);
        }
        const float* wa = wn0 + ch * 64 + kk;
        const float* wb = wn1 + ch * 64 + kk;
#pragma unroll
        for (int ks = 0; ks < 4; ks++) {
            const int kx = kk + ks * 8;
            uint32_t A0 = __float_as_uint(hs[ar0 + kx + tig]);
            uint32_t A1 = __float_as_uint(hs[ar1 + kx + tig]);
            uint32_t A2 = __float_as_uint(hs[ar0 + kx + tig + 4]);
            uint32_t A3 = __float_as_uint(hs[ar1 + kx + tig + 4]);
            uint32_t B0 = __float_as_uint(wa[ks * 8 + tig]);
            uint32_t B1 = __float_as_uint(wa[ks * 8 + tig + 4]);
            mma8(acc, A0, A1, A2, A3, B0, B1);
            uint32_t B2 = __float_as_uint(wb[ks * 8 + tig]);
            uint32_t B3 = __float_as_uint(wb[ks * 8 + tig + 4]);
            mma8(acc + 4, A0, A1, A2, A3, B2, B3);
        }
    }

    // K-half reduction (kh=1 -> SMEM, kh=0 adds) + bias + tanh + store
    __syncthreads();
    if (kh == 1) {
#pragma unroll
        for (int nt = 0; nt < 2; nt++) {
            const int cl = wc * 16 + nt * 8 + 2 * tig;
            *(float2*)&hs[(wr*16 + g)     * SE + cl] = make_float2(acc[nt*4+0], acc[nt*4+1]);
            *(float2*)&hs[(wr*16 + g + 8) * SE + cl] = make_float2(acc[nt*4+2], acc[nt*4+3]);
        }
    }
    __syncthreads();
    if (kh == 0) {
#pragma unroll
        for (int nt = 0; nt < 2; nt++) {
            const int cl = wc * 16 + nt * 8 + 2 * tig;
            float2 p0 = *(float2*)&hs[(wr*16 + g)     * SE + cl];
            float2 p1 = *(float2*)&hs[(wr*16 + g + 8) * SE + cl];
            float o0 = tanhf(acc[nt*4+0] + p0.x + bs[cl]);
            float o1 = tanhf(acc[nt*4+1] + p0.y + bs[cl + 1]);
            float o2 = tanhf(acc[nt*4+2] + p1.x + bs[cl]);
            float o3 = tanhf(acc[nt*4+3] + p1.y + bs[cl + 1]);
            *(float2*)&dst[(size_t)(rbase + wr*16 + g)     * H + colbase + cl] = make_float2(o0, o1);
            *(float2*)&dst[(size_t)(rbase + wr*16 + g + 8) * H + colbase + cl] = make_float2(o2, o3);
        }
    }
}

// ---------------------------------------------------------------------------
__global__ void __launch_bounds__(NTHREADS, 1)
rnn_kernel(const float* __restrict__ cat_seq, const float* __restrict__ val_seq,
           const float* __restrict__ W_ih0, const float* __restrict__ W_hh0,
           const float* __restrict__ b0,
           const float* __restrict__ W_ih1, const float* __restrict__ W_hh1,
           const float* __restrict__ b1,
           const float* __restrict__ Wc, const float* __restrict__ bc,
           const float* __restrict__ Wm, const float* __restrict__ bm,
           float* __restrict__ out)
{
    extern __shared__ float sm[];
    float* W0s = sm + OFF_W0;
    float* W1s = sm + OFF_W1;
    float* hs  = sm + OFF_HS;
    float* Wms = sm + OFF_WM;
    float* bs0 = sm + OFF_B0;
    float* bs1 = sm + OFF_B1;
    float* slg = sm + OFF_LG;

    const int tid = threadIdx.x;
    const int cta = blockIdx.x;
    const int ri  = cta >> 4;
    const int cj  = cta & 15;
    const int rbase   = ri * 32;
    const int colbase = cj * 32;

    // ---- per-launch init ----
    {
        int gt = cta * NTHREADS + tid;
        for (int i = gt; i < BATCH * H; i += GRIDN * NTHREADS) {
            g_h0[0][i] = 0.f;
            g_h1[0][i] = 0.f;
        }
        for (int i = gt; i < BATCH * 128; i += GRIDN * NTHREADS) {
            int r = i >> 7, s = i & 127;
            float v = 0.f;
            if (s < NC)           v = cat_seq[r * NC + s];
            else if (s < NC + NM) v = val_seq[r * NM + (s - NC)];
            g_Xp[i] = v;
        }
        for (int i = gt; i < NC * H; i += GRIDN * NTHREADS) {
            int j = i >> 9, k = i & (H - 1);
            g_Wct[i] = Wc[k * NC + j];
        }
    }

    // ---- SMEM weight slices (transposed, k-contiguous, tf32-rounded) ----
    for (int idx = tid; idx < 32 * SA; idx += NTHREADS) {
        int c = idx / SA, k = idx - c * SA;
        float v = 0.f;
        if (k < NC + NM)              v = W_ih0[k * H + colbase + c];
        else if (k >= 128 && k < 640) v = W_hh0[(k - 128) * H + colbase + c];
        W0s[idx] = __uint_as_float(tf32r(v));
    }
    for (int idx = tid; idx < 32 * SB; idx += NTHREADS) {
        int c = idx / SB, k = idx - c * SB;
        float v = 0.f;
        if (k < H)         v = W_ih1[k * H + colbase + c];
        else if (k < 2*H)  v = W_hh1[(k - H) * H + colbase + c];
        W1s[idx] = __uint_as_float(tf32r(v));
    }
    if (tid < 32) { bs0[tid] = b0[colbase + tid]; bs1[tid] = b1[colbase + tid]; }
    for (int idx = tid; idx < 4 * H; idx += NTHREADS) {
        int c = idx >> 9, k = idx & (H - 1);
        Wms[c * SWM + k] = Wm[k * NM + (cj << 2) + c];
    }
    gridbar();

    const int vr = tid >> 2, vc = tid & 3;
    const int t2 = tid - 128;
    const int rl = (t2 >= 0) ? t2 / 3 : 0, jj = (t2 >= 0) ? t2 - rl * 3 : 0;
    const int srow = tid >> 3, sinner = (tid & 7) << 3;

    // preload phase-A chunks (START_A, START_A+1) for t=0
    float4 pAa0, pAb0, pAa1, pAb1;
    ld_chunk(g_Xp, 128, SPLIT_A, g_h0[0], H, START_A,     rbase, srow, sinner, pAa0, pAb0);
    ld_chunk(g_Xp, 128, SPLIT_A, g_h0[0], H, START_A + 1, rbase, srow, sinner, pAa1, pAb1);

    // ---- time loop ----
    for (int t = 0; t < T_STEPS; t++) {
        const int p = t & 1;
        const float* H0r = g_h0[p];   float* H0w = g_h0[p ^ 1];
        const float* H1r = g_h1[p];   float* H1w = g_h1[p ^ 1];

        // Phase A
        mm_phase(g_Xp, 128, SPLIT_A, H0r, H, NCH_A, START_A,
                 pAa0, pAb0, pAa1, pAb1, W0s, SA, bs0, hs, H0w, rbase, colbase);

        // preload phase-B chunks from H1r (stable) BEFORE barrier
        float4 pBa0, pBb0, pBa1, pBb1;
        ld_chunk(H0w, H, SPLIT_B, H1r, H, START_B,     rbase, srow, sinner, pBa0, pBb0);
        ld_chunk(H0w, H, SPLIT_B, H1r, H, START_B + 1, rbase, srow, sinner, pBa1, pBb1);
        gridbar();

        // Phase B
        mm_phase(H0w, H, SPLIT_B, H1r, H, NCH_B, START_B,
                 pBa0, pBb0, pBa1, pBb1, W1s, SB, bs1, hs, H1w, rbase, colbase);
        gridbar();

        // Phase C: heads + softmax + impute (fp32, staged via SMEM)
        {
            float acc = 0.f;
            float4 a0, b0, a1, b1;
            ld_chunk(H1w, H, 8, H1w, H, 0, rbase, srow, sinner, a0, b0);
            ld_chunk(H1w, H, 8, H1w, H, 1, rbase, srow, sinner, a1, b1);
            for (int ch = 0; ch < 8; ch++) {
                __syncthreads();
                *(float4*)(hs + srow * SH + sinner)     = a0;
                *(float4*)(hs + srow * SH + sinner + 4) = b0;
                __syncthreads();
                a0 = a1; b0 = b1;
                if (ch + 2 < 8)
                    ld_chunk(H1w, H, 8, H1w, H, ch + 2, rbase, srow, sinner, a1, b1);
                if (tid < 128) {
                    const float* hp = hs + vr * SH;
                    const float* wp = Wms + vc * SWM + ch * 64;
#pragma unroll
                    for (int q = 0; q < 16; q++) {
                        float4 h4 = *(const float4*)(hp + (q << 2));
                        float4 w4 = *(const float4*)(wp + (q << 2));
                        acc = fmaf(h4.x, w4.x, fmaf(h4.y, w4.y,
                              fmaf(h4.z, w4.z, fmaf(h4.w, w4.w, acc))));
                    }
                } else if (cj == 0 && tid < 224) {
                    const float* hp = hs + rl * SH;
                    const float* wp = g_Wct + jj * H + ch * 64;
#pragma unroll
                    for (int q = 0; q < 16; q++) {
                        float4 h4 = *(const float4*)(hp + (q << 2));
                        float4 w4 = *(const float4*)(wp + (q << 2));
                        acc = fmaf(h4.x, w4.x, fmaf(h4.y, w4.y,
                              fmaf(h4.z, w4.z, fmaf(h4.w, w4.w, acc))));
                    }
                }
            }
            if (cj == 0 && tid >= 128 && tid < 224)
                slg[t2] = acc + __ldg(bc + jj);
            __syncthreads();
            if (tid < 128) {
                int ccol = (cj << 2) + vc;
                int r = rbase + vr;
                float v   = acc + __ldg(bm + ccol) + g_Xp[r * 128 + NC + ccol];
                float nxt = val_seq[(size_t)(t + 1) * BATCH * NM + r * NM + ccol];
                g_Xp[r * 128 + NC + ccol] = (nxt != nxt) ? v : nxt;
            } else if (cj == 0 && tid < 224) {
                float l0 = slg[rl * 3 + 0], l1 = slg[rl * 3 + 1], l2 = slg[rl * 3 + 2];
                float m  = fmaxf(l0, fmaxf(l1, l2));
                float e0 = expf(l0 - m), e1 = expf(l1 - m), e2 = expf(l2 - m);
                float s  = e0 + e1 + e2;
                float oc = ((jj == 0) ? e0 : (jj == 1) ? e1 : e2) / s;
                int r = rbase + rl;
                out[(size_t)t * BATCH * NC + r * NC + jj] = oc;
                float nxt = cat_seq[(size_t)(t + 1) * BATCH * NC + r * NC + jj];
                g_Xp[r * 128 + jj] = (nxt != nxt) ? oc : nxt;
            }
        }
        // preload next step's phase-A chunks (H0w stable)
        if (t + 1 < T_STEPS) {
            ld_chunk(g_Xp, 128, SPLIT_A, H0w, H, START_A,     rbase, srow, sinner, pAa0, pAb0);
            ld_chunk(g_Xp, 128, SPLIT_A, H0w, H, START_A + 1, rbase, srow, sinner, pAa1, pAb1);
        }
        gridbar();
    }
}

// ---------------------------------------------------------------------------
extern "C" void kernel_launch(void* const* d_in, const int* in_sizes, int n_in,
                              void* d_out, int out_size)
{
    (void)in_sizes; (void)n_in; (void)out_size;
    cudaFuncSetAttribute(rnn_kernel,
                         cudaFuncAttributeMaxDynamicSharedMemorySize, SMEM_BYTES);
    rnn_kernel<<<GRIDN, NTHREADS, SMEM_BYTES>>>(
        (const float*)d_in[0],  (const float*)d_in[1],
        (const float*)d_in[2],  (const float*)d_in[3],  (const float*)d_in[4],
        (const float*)d_in[5],  (const float*)d_in[6],  (const float*)d_in[7],
        (const float*)d_in[8],  (const float*)d_in[9],
        (const float*)d_in[10], (const float*)d_in[11],
        (float*)d_out);
}